// round 16
// baseline (speedup 1.0000x reference)
#include <cuda_runtime.h>
#include <cuda_fp16.h>
#include <cstdint>

#define HW   4096
#define NIMG 32

// ---------------- device scratch (no allocations allowed) ----------------
__device__ float  g_c1  [32u *  64u * 4096u];   // conv1 out (NCHW f32, deform2 src)
// fp16 NHWC operands
__device__ __half g_xf16[32u * 4096u * 256u];   // x NHWC fp16 (off1 A)
__device__ __half g_cf16[32u * 4096u * 64u];    // conv1 out NHWC fp16 (off2 A)
__device__ __half g_dh1 [32u * 4096u * 256u];   // deform1 out NHWC fp16 (conv1 A)
__device__ __half g_dh2 [32u * 4096u * 64u];    // deform2 out NHWC fp16 (conv2 A)
// weights [oc][tap][ic] fp16
__device__ __half g_wf16[1253376];              // w_off1 @0, w_off2 @1179648
#define WF_OFF1 0
#define WF_OFF2 1179648
__device__ __half g_wfh[184320];                // w1 @0, w2 @147456 (hi)
__device__ __half g_wfl[184320];                // (lo)
#define WB_C1 0
#define WB_C2 147456

// ---------------- helpers ----------------
__device__ __forceinline__ uint32_t smem_u32(const void* p) {
    uint32_t a;
    asm("{ .reg .u64 t; cvta.to.shared.u64 t, %1; cvt.u32.u64 %0, t; }"
        : "=r"(a) : "l"(p));
    return a;
}
__device__ __forceinline__ void ldsm_x4(uint32_t& r0, uint32_t& r1,
                                        uint32_t& r2, uint32_t& r3, uint32_t addr) {
    asm volatile("ldmatrix.sync.aligned.m8n8.x4.shared.b16 {%0,%1,%2,%3}, [%4];"
                 : "=r"(r0), "=r"(r1), "=r"(r2), "=r"(r3) : "r"(addr));
}
__device__ __forceinline__ void mma_f16(float* c, const uint32_t* a,
                                        const uint32_t* b) {
    asm volatile(
        "mma.sync.aligned.m16n8k16.row.col.f32.f16.f16.f32 "
        "{%0,%1,%2,%3}, {%4,%5,%6,%7}, {%8,%9}, {%0,%1,%2,%3};"
        : "+f"(c[0]), "+f"(c[1]), "+f"(c[2]), "+f"(c[3])
        : "r"(a[0]), "r"(a[1]), "r"(a[2]), "r"(a[3]), "r"(b[0]), "r"(b[1]));
}
__device__ __forceinline__ void cpa16(uint32_t dst, const void* src, uint32_t sz) {
    asm volatile("cp.async.cg.shared.global [%0], [%1], 16, %2;"
                 :: "r"(dst), "l"(src), "r"(sz));
}
#define CPA_COMMIT() asm volatile("cp.async.commit_group;" ::: "memory")
#define CPA_WAIT1()  asm volatile("cp.async.wait_group 1;" ::: "memory")

#define ROWB 144   // smem row stride (9x16B -> conflict-free ldmatrix)

// ---------------- prep: x -> NHWC fp16 ----------------
__global__ void k_prep_x16(const float* __restrict__ x, __half* __restrict__ xf)
{
    __shared__ float sm[32][33];
    int n    = blockIdx.z;
    int c0   = blockIdx.y << 5;
    int pix0 = blockIdx.x << 5;
    int tx = threadIdx.x, ty = threadIdx.y;
    int b = n >> 3, t = n & 7;
#pragma unroll
    for (int q = 0; q < 4; q++) {
        int c = c0 + ty + q * 8;
        sm[ty + q * 8][tx] = x[((((long long)b * 256 + c) * 8 + t) << 12) + pix0 + tx];
    }
    __syncthreads();
#pragma unroll
    for (int q = 0; q < 4; q++) {
        int pix = pix0 + ty + q * 8;
        xf[((long long)n * 4096 + pix) * 256 + c0 + tx] = __float2half(sm[tx][ty + q * 8]);
    }
}

// ---------------- prep: ALL weights in one launch ----------------
__global__ void k_prep_w_all(const float* __restrict__ w_off1, const float* __restrict__ w1,
                             const float* __restrict__ w_off2, const float* __restrict__ w2,
                             __half* __restrict__ wf16,
                             __half* __restrict__ wfh, __half* __restrict__ wfl)
{
    int i = blockIdx.x * 256 + threadIdx.x;
    if (i >= 1437696) return;
    const float* src;
    __half *dst_s = nullptr, *dst_h = nullptr, *dst_l = nullptr;
    int j, Cin;
    if (i < 1179648)      { j = i;           Cin = 256; src = w_off1; dst_s = wf16 + WF_OFF1 + j; }
    else if (i < 1253376) { j = i - 1179648; Cin = 64;  src = w_off2; dst_s = wf16 + WF_OFF2 + j; }
    else if (i < 1400832) { j = i - 1253376; Cin = 256; src = w1;     dst_h = wfh + WB_C1 + j; dst_l = wfl + WB_C1 + j; }
    else                  { j = i - 1400832; Cin = 64;  src = w2;     dst_h = wfh + WB_C2 + j; dst_l = wfl + WB_C2 + j; }
    int oc  = j / (Cin * 9);
    int r   = j - oc * (Cin * 9);
    int tap = r / Cin;
    int ic  = r - tap * Cin;
    float v = src[(long long)(oc * Cin + ic) * 9 + tap];
    if (dst_s) {
        *dst_s = __float2half(v);
    } else {
        __half hi = __float2half(v);
        *dst_h = hi;
        *dst_l = __float2half(v - __half2float(hi));
    }
}

// ---------------- staging ----------------
template<int MI>
__device__ __forceinline__ void stage_A(
    uint32_t abase, int tid, int ic0, int n, int y0, int Cin,
    const __half* __restrict__ xA)
{
    constexpr int AR = (MI + 2) * 66;
    for (int i = tid; i < AR * 8; i += 256) {
        int row = i >> 3, u = i & 7;
        int rel_y = row / 66, rel_x = row - rel_y * 66;
        int ys = y0 - 1 + rel_y, xs = rel_x - 1;
        bool ok = ((unsigned)ys < 64u) && ((unsigned)xs < 64u);
        const __half* src = ok ?
            xA + (((long long)n * 4096 + ys * 64 + xs) * Cin + ic0 + (u << 3)) : xA;
        cpa16(abase + row * ROWB + (u << 4), src, ok ? 16u : 0u);
    }
}

// stage 3 taps of B: layout [pre][tap_local][oc_row]
template<int NOC, bool BSPL>
__device__ __forceinline__ void stage_B3(
    uint32_t bbase, int tid, int trio, int ic0, int oc0, int Cin,
    const __half* __restrict__ wh, const __half* __restrict__ wl)
{
    constexpr int PLANE = 3 * NOC * 8;
    const int TOT = PLANE * (BSPL ? 2 : 1);
    for (int i = tid; i < TOT; i += 256) {
        int pre = BSPL ? (i >= PLANE) : 0;
        int f   = i - pre * PLANE;
        int tl  = f / (NOC * 8);
        int g   = f - tl * (NOC * 8);
        int r = g >> 3, u = g & 7;
        int tap = trio * 3 + tl;
        const __half* src = (pre ? wl : wh) +
            ((long long)(oc0 + r) * 9 + tap) * Cin + ic0 + (u << 3);
        cpa16(bbase + (pre * 3 + tl) * (NOC * ROWB) + r * ROWB + (u << 4), src, 16u);
    }
}

// ---------------- mma implicit-GEMM conv: D[64*MI px][NOC oc] ----------------
// A halo plane double-buffered by ic64 parity; tap shift via fragment address.
// B trio double-buffered by stage parity; uniform WAIT1 pipeline.
// BSPL: w hi/lo -> 2 passes (value convs).
// DEFORM: fused ConvOffset2D epilogue. The reshape(N*C,H,W,2) view means the
//   offset value at NCHW (ch, q) is component k=q&1 of sampling pixel
//   p = (ch&1)*2048 + (q>>1) for image channel c = ch>>1. (y,x) pairs are
//   adjacent in q -> exchanged via shfl_xor(4) (lanes qrow^1).
template<int NOC, int MI, bool BSPL, bool DEFORM>
__global__ __launch_bounds__(256)
void k_conv_mma(const __half* __restrict__ xA,
                const __half* __restrict__ wh, const __half* __restrict__ wl,
                float* __restrict__ out_f32, __half* __restrict__ out_h16,
                const float* __restrict__ defsrc, __half* __restrict__ defdst,
                int isX,
                const float* __restrict__ bng, const float* __restrict__ bnb,
                const float* __restrict__ bnm, const float* __restrict__ bnv,
                int Cin, int Cout, int outTrans)
{
    extern __shared__ __align__(16) char smc[];
    const uint32_t uS = smem_u32(smc);

    constexpr int NT = 64 / MI;
    constexpr int AB = (MI + 2) * 66 * ROWB;
    constexpr int BB = 3 * NOC * ROWB * (BSPL ? 2 : 1);
    constexpr int J2 = NOC / 32;

    const int tid  = threadIdx.x;
    const int lane = tid & 31;
    const int wid  = tid >> 5;
    const int wm   = wid >> 1;
    const int wn   = wid & 1;

    const int n   = blockIdx.x / NT;
    const int mt  = blockIdx.x - n * NT;
    const int y0  = mt * MI;
    const int oc0 = blockIdx.y * NOC;
    const int nic = Cin >> 6;
    const int nstage = 3 * nic;

    float acc[MI][J2 * 2][4];
#pragma unroll
    for (int i = 0; i < MI; i++)
#pragma unroll
        for (int j = 0; j < J2 * 2; j++)
#pragma unroll
            for (int q = 0; q < 4; q++) acc[i][j][q] = 0.f;

    const int aOff = (lane >> 4) << 4;
    int rowoff[MI];
#pragma unroll
    for (int i = 0; i < MI; i++) {
        int m = wm * (16 * MI) + (lane & 15) + i * 16;
        rowoff[i] = (((m >> 6) + 1) * 66 + (m & 63) + 1) * ROWB;
    }
    const int bRow = wn * (NOC >> 1) + (lane & 7) + ((lane >> 4) << 3);
    const int bOff = ((lane >> 3) & 1) << 4;

    const uint32_t uA[2] = {uS, uS + AB};
    const uint32_t uB[2] = {uS + 2 * AB, uS + 2 * AB + BB};

    stage_A<MI>(uA[0], tid, 0, n, y0, Cin, xA);
    stage_B3<NOC, BSPL>(uB[0], tid, 0, 0, oc0, Cin, wh, wl);
    CPA_COMMIT();

    for (int s = 0; s < nstage; s++) {
        const int icc  = s / 3;
        const int trio = s - icc * 3;
        const int nx = s + 1;
        if (nx < nstage) {
            const int nicc = nx / 3;
            const int ntrio = nx - nicc * 3;
            if (ntrio == 0)
                stage_A<MI>(uA[nicc & 1], tid, nicc << 6, n, y0, Cin, xA);
            stage_B3<NOC, BSPL>(uB[nx & 1], tid, ntrio, nicc << 6, oc0, Cin, wh, wl);
        }
        CPA_COMMIT();
        CPA_WAIT1();
        __syncthreads();

        const uint32_t aBase = uA[icc & 1];
        const uint32_t bBase = uB[s & 1];
#pragma unroll
        for (int tl = 0; tl < 3; tl++) {
            const int tap = trio * 3 + tl;
            const int d144 = ((tap / 3) * 66 + (tap - (tap / 3) * 3) - 67) * ROWB;
            const uint32_t aH = aBase + d144;
            const uint32_t bH = bBase + tl * (NOC * ROWB);
            const uint32_t bL = bBase + (3 + tl) * (NOC * ROWB);

#pragma unroll
            for (int ks = 0; ks < 4; ks++) {
                const int kbyte = ks * 32;
                uint32_t ah[MI][4], bh[J2][4];
#pragma unroll
                for (int i = 0; i < MI; i++)
                    ldsm_x4(ah[i][0], ah[i][1], ah[i][2], ah[i][3],
                            aH + rowoff[i] + kbyte + aOff);
#pragma unroll
                for (int j2 = 0; j2 < J2; j2++)
                    ldsm_x4(bh[j2][0], bh[j2][1], bh[j2][2], bh[j2][3],
                            bH + (bRow + j2 * 16) * ROWB + kbyte + bOff);
#pragma unroll
                for (int i = 0; i < MI; i++)
#pragma unroll
                    for (int j2 = 0; j2 < J2; j2++) {
                        mma_f16(acc[i][j2 * 2 + 0], ah[i], &bh[j2][0]);
                        mma_f16(acc[i][j2 * 2 + 1], ah[i], &bh[j2][2]);
                    }
                if constexpr (BSPL) {
                    uint32_t bl[J2][4];
#pragma unroll
                    for (int j2 = 0; j2 < J2; j2++)
                        ldsm_x4(bl[j2][0], bl[j2][1], bl[j2][2], bl[j2][3],
                                bL + (bRow + j2 * 16) * ROWB + kbyte + bOff);
#pragma unroll
                    for (int i = 0; i < MI; i++)
#pragma unroll
                        for (int j2 = 0; j2 < J2; j2++) {
                            mma_f16(acc[i][j2 * 2 + 0], ah[i], &bl[j2][0]);
                            mma_f16(acc[i][j2 * 2 + 1], ah[i], &bl[j2][2]);
                        }
                }
            }
        }
        __syncthreads();
    }

    // ---------------- epilogue ----------------
    const int qrow = lane >> 2;
    const int qcol = (lane & 3) << 1;
    const long long pixbase = (long long)mt * (64 * MI) + wm * (16 * MI);
    const int b = n >> 3, tt = n & 7;

    if constexpr (DEFORM) {
        const int C = Cout >> 1;
        const bool even = !(qrow & 1);
#pragma unroll
        for (int j = 0; j < J2 * 2; j++) {
            int oc = oc0 + wn * (NOC >> 1) + j * 8 + qcol;   // even column
            int c  = oc >> 1;                                 // image channel
            const float* xc = isX
                ? defsrc + ((((long long)b * 256 + c) * 8 + tt) << 12)
                : defsrc + (((long long)n * C + c) << 12);
#pragma unroll
            for (int i = 0; i < MI; i++) {
                // exchange with lane^4 (qrow parity partner)
                float r0 = __shfl_xor_sync(0xffffffffu, acc[i][j][0], 4);
                float r1 = __shfl_xor_sync(0xffffffffu, acc[i][j][1], 4);
                float r2 = __shfl_xor_sync(0xffffffffu, acc[i][j][2], 4);
                float r3 = __shfl_xor_sync(0xffffffffu, acc[i][j][3], 4);
                long long q_e = pixbase + i * 16 + (qrow & ~1);
                long long ph  = q_e >> 1;
                // each thread produces 2 samples (pair covers 4 per 2 threads)
                float oyA, oxA, oyB, oxB;
                long long pA, pB;
                if (even) {
                    oyA = acc[i][j][0]; oxA = r0; pA = ph;          // ch=oc
                    oyB = acc[i][j][1]; oxB = r1; pB = 2048 + ph;   // ch=oc+1
                } else {
                    oyA = r2; oxA = acc[i][j][2]; pA = ph + 4;
                    oyB = r3; oxB = acc[i][j][3]; pB = 2048 + ph + 4;
                }
#pragma unroll
                for (int s2 = 0; s2 < 2; s2++) {
                    long long p = s2 ? pB : pA;
                    float oy = s2 ? oyB : oyA;
                    float ox = s2 ? oxB : oxA;
                    int h = (int)(p >> 6), w = (int)(p & 63);
                    float cy = fminf(fmaxf((float)h + oy, 0.f), 63.f);
                    float cx = fminf(fmaxf((float)w + ox, 0.f), 63.f);
                    float y0f = floorf(cy), x0f = floorf(cx);
                    float ty = cy - y0f, txq = cx - x0f;
                    int yy0 = (int)y0f, xx0 = (int)x0f;
                    int yy1 = min(yy0 + 1, 63), xx1 = min(xx0 + 1, 63);
                    float v00 = xc[(yy0 << 6) + xx0];
                    float v01 = xc[(yy0 << 6) + xx1];
                    float v10 = xc[(yy1 << 6) + xx0];
                    float v11 = xc[(yy1 << 6) + xx1];
                    float r = v00 * (1.f - ty) * (1.f - txq) + v01 * (1.f - ty) * txq +
                              v10 * ty * (1.f - txq)         + v11 * ty * txq;
                    defdst[((long long)n * 4096 + p) * C + c] = __float2half(r);
                }
            }
        }
    } else {
        const bool dobn = (bng != nullptr);
#pragma unroll
        for (int i = 0; i < MI; i++) {
#pragma unroll
            for (int j = 0; j < J2 * 2; j++) {
                int oc = oc0 + wn * (NOC >> 1) + j * 8 + qcol;
                long long p0 = pixbase + i * 16 + qrow;
                float v0 = acc[i][j][0], v1 = acc[i][j][1];
                float v2 = acc[i][j][2], v3 = acc[i][j][3];
                if (dobn) {
                    float sc0 = bng[oc] * rsqrtf(bnv[oc] + 1e-5f);
                    float bi0 = bnb[oc] - bnm[oc] * sc0;
                    float sc1 = bng[oc + 1] * rsqrtf(bnv[oc + 1] + 1e-5f);
                    float bi1 = bnb[oc + 1] - bnm[oc + 1] * sc1;
                    v0 = v0 * sc0 + bi0; v0 = (v0 > 0.f) ? v0 : 0.01f * v0;
                    v1 = v1 * sc1 + bi1; v1 = (v1 > 0.f) ? v1 : 0.01f * v1;
                    v2 = v2 * sc0 + bi0; v2 = (v2 > 0.f) ? v2 : 0.01f * v2;
                    v3 = v3 * sc1 + bi1; v3 = (v3 > 0.f) ? v3 : 0.01f * v3;
                }
                if (out_f32) {
                    long long o0, o1;
                    if (outTrans) {
                        o0 = ((((long long)b * Cout + oc) * 8 + tt) << 12) + p0;
                        o1 = ((((long long)b * Cout + oc + 1) * 8 + tt) << 12) + p0;
                    } else {
                        o0 = (((long long)n * Cout + oc) << 12) + p0;
                        o1 = (((long long)n * Cout + oc + 1) << 12) + p0;
                    }
                    out_f32[o0]     = v0;
                    out_f32[o1]     = v1;
                    out_f32[o0 + 8] = v2;
                    out_f32[o1 + 8] = v3;
                }
                if (out_h16) {
                    long long q0 = ((long long)n * 4096 + p0) * Cout + oc;
                    long long q1 = ((long long)n * 4096 + p0 + 8) * Cout + oc;
                    *(__half2*)(out_h16 + q0) = __floats2half2_rn(v0, v1);
                    *(__half2*)(out_h16 + q1) = __floats2half2_rn(v2, v3);
                }
            }
        }
    }
}

// ---------------- launch ----------------
extern "C" void kernel_launch(void* const* d_in, const int* in_sizes, int n_in,
                              void* d_out, int out_size)
{
    const float* x      = (const float*)d_in[0];
    const float* w_off1 = (const float*)d_in[3];
    const float* w1     = (const float*)d_in[4];
    const float* g1     = (const float*)d_in[5];
    const float* b1     = (const float*)d_in[6];
    const float* m1     = (const float*)d_in[7];
    const float* v1     = (const float*)d_in[8];
    const float* w_off2 = (const float*)d_in[9];
    const float* w2     = (const float*)d_in[10];
    const float* g2     = (const float*)d_in[11];
    const float* b2     = (const float*)d_in[12];
    const float* m2     = (const float*)d_in[13];
    const float* v2     = (const float*)d_in[14];
    float* out = (float*)d_out;

    float *c1;
    __half *xf16, *cf16, *dh1, *dh2, *wf16, *wfh, *wfl;
    cudaGetSymbolAddress((void**)&c1,   g_c1);
    cudaGetSymbolAddress((void**)&xf16, g_xf16);
    cudaGetSymbolAddress((void**)&cf16, g_cf16);
    cudaGetSymbolAddress((void**)&dh1,  g_dh1);
    cudaGetSymbolAddress((void**)&dh2,  g_dh2);
    cudaGetSymbolAddress((void**)&wf16, g_wf16);
    cudaGetSymbolAddress((void**)&wfh,  g_wfh);
    cudaGetSymbolAddress((void**)&wfl,  g_wfl);

    const int SM_ALL = 2 * 6 * 66 * ROWB + 2 * 3 * 128 * ROWB;   // 224640

    cudaFuncSetAttribute(k_conv_mma<128, 4, false, true>,
                         cudaFuncAttributeMaxDynamicSharedMemorySize, SM_ALL);
    cudaFuncSetAttribute(k_conv_mma<64, 4, true, false>,
                         cudaFuncAttributeMaxDynamicSharedMemorySize, SM_ALL);

    // preps
    k_prep_x16<<<dim3(128, 8, NIMG), dim3(32, 8)>>>(x, xf16);
    k_prep_w_all<<<(1437696 + 255) / 256, 256>>>(w_off1, w1, w_off2, w2, wf16, wfh, wfl);

    // off1 + fused deform1: 256 -> 512 offsets -> bilinear(x) -> dh1 fp16 NHWC
    k_conv_mma<128, 4, false, true><<<dim3(NIMG * 16, 4), 256, SM_ALL>>>(
        xf16, wf16 + WF_OFF1, nullptr, nullptr, nullptr,
        x, dh1, 1,
        nullptr, nullptr, nullptr, nullptr, 256, 512, 0);

    // conv1 + bn1 + lrelu: 256 -> 64 (2-pass w-split; f32 NCHW + fp16 NHWC out)
    k_conv_mma<64, 4, true, false><<<dim3(NIMG * 16, 1), 256, SM_ALL>>>(
        dh1, wfh + WB_C1, wfl + WB_C1, c1, cf16,
        nullptr, nullptr, 0,
        g1, b1, m1, v1, 256, 64, 0);

    // off2 + fused deform2: 64 -> 128 offsets -> bilinear(c1) -> dh2 fp16 NHWC
    k_conv_mma<128, 4, false, true><<<dim3(NIMG * 16, 1), 256, SM_ALL>>>(
        cf16, wf16 + WF_OFF2, nullptr, nullptr, nullptr,
        c1, dh2, 0,
        nullptr, nullptr, nullptr, nullptr, 64, 128, 0);

    // conv2 + bn2 + lrelu + transpose: 64 -> 64 (2-pass)
    k_conv_mma<64, 4, true, false><<<dim3(NIMG * 16, 1), 256, SM_ALL>>>(
        dh2, wfh + WB_C2, wfl + WB_C2, out, nullptr,
        nullptr, nullptr, 0,
        g2, b2, m2, v2, 64, 64, 1);
}

// round 17
// speedup vs baseline: 1.0247x; 1.0247x over previous
#include <cuda_runtime.h>
#include <cuda_fp16.h>
#include <cstdint>

#define HW   4096
#define NIMG 32

// ---------------- device scratch (no allocations allowed) ----------------
__device__ __half g_off1h[32u * 512u * 4096u];  // offsets 1 (NCHW fp16)
__device__ float  g_c1   [32u *  64u * 4096u];  // conv1 out (NCHW f32, deform2 src)
__device__ __half g_off2h[32u * 128u * 4096u];  // offsets 2 (NCHW fp16)
// fp16 NHWC operands
__device__ __half g_xf16[32u * 4096u * 256u];   // x NHWC fp16 (off1 A)
__device__ __half g_cf16[32u * 4096u * 64u];    // conv1 out NHWC fp16 (off2 A)
__device__ __half g_dh1 [32u * 4096u * 256u];   // deform1 out NHWC fp16 (conv1 A)
__device__ __half g_dh2 [32u * 4096u * 64u];    // deform2 out NHWC fp16 (conv2 A)
// weights [oc][tap][ic] fp16
__device__ __half g_wf16[1253376];              // w_off1 @0, w_off2 @1179648
#define WF_OFF1 0
#define WF_OFF2 1179648
__device__ __half g_wfh[184320];                // w1 @0, w2 @147456 (hi)
__device__ __half g_wfl[184320];                // (lo)
#define WB_C1 0
#define WB_C2 147456

// ---------------- helpers ----------------
__device__ __forceinline__ uint32_t smem_u32(const void* p) {
    uint32_t a;
    asm("{ .reg .u64 t; cvta.to.shared.u64 t, %1; cvt.u32.u64 %0, t; }"
        : "=r"(a) : "l"(p));
    return a;
}
__device__ __forceinline__ void ldsm_x4(uint32_t& r0, uint32_t& r1,
                                        uint32_t& r2, uint32_t& r3, uint32_t addr) {
    asm volatile("ldmatrix.sync.aligned.m8n8.x4.shared.b16 {%0,%1,%2,%3}, [%4];"
                 : "=r"(r0), "=r"(r1), "=r"(r2), "=r"(r3) : "r"(addr));
}
__device__ __forceinline__ void mma_f16(float* c, const uint32_t* a,
                                        const uint32_t* b) {
    asm volatile(
        "mma.sync.aligned.m16n8k16.row.col.f32.f16.f16.f32 "
        "{%0,%1,%2,%3}, {%4,%5,%6,%7}, {%8,%9}, {%0,%1,%2,%3};"
        : "+f"(c[0]), "+f"(c[1]), "+f"(c[2]), "+f"(c[3])
        : "r"(a[0]), "r"(a[1]), "r"(a[2]), "r"(a[3]), "r"(b[0]), "r"(b[1]));
}
__device__ __forceinline__ void cpa16(uint32_t dst, const void* src, uint32_t sz) {
    asm volatile("cp.async.cg.shared.global [%0], [%1], 16, %2;"
                 :: "r"(dst), "l"(src), "r"(sz));
}
#define CPA_COMMIT() asm volatile("cp.async.commit_group;" ::: "memory")
#define CPA_WAIT1()  asm volatile("cp.async.wait_group 1;" ::: "memory")

#define ROWB 144   // smem row stride (9x16B -> conflict-free ldmatrix)

// ---------------- prep: x -> NHWC fp16 ----------------
__global__ void k_prep_x16(const float* __restrict__ x, __half* __restrict__ xf)
{
    __shared__ float sm[32][33];
    int n    = blockIdx.z;
    int c0   = blockIdx.y << 5;
    int pix0 = blockIdx.x << 5;
    int tx = threadIdx.x, ty = threadIdx.y;
    int b = n >> 3, t = n & 7;
#pragma unroll
    for (int q = 0; q < 4; q++) {
        int c = c0 + ty + q * 8;
        sm[ty + q * 8][tx] = x[((((long long)b * 256 + c) * 8 + t) << 12) + pix0 + tx];
    }
    __syncthreads();
#pragma unroll
    for (int q = 0; q < 4; q++) {
        int pix = pix0 + ty + q * 8;
        xf[((long long)n * 4096 + pix) * 256 + c0 + tx] = __float2half(sm[tx][ty + q * 8]);
    }
}

// ---------------- prep: ALL weights in one launch ----------------
__global__ void k_prep_w_all(const float* __restrict__ w_off1, const float* __restrict__ w1,
                             const float* __restrict__ w_off2, const float* __restrict__ w2,
                             __half* __restrict__ wf16,
                             __half* __restrict__ wfh, __half* __restrict__ wfl)
{
    int i = blockIdx.x * 256 + threadIdx.x;
    if (i >= 1437696) return;
    const float* src;
    __half *dst_s = nullptr, *dst_h = nullptr, *dst_l = nullptr;
    int j, Cin;
    if (i < 1179648)      { j = i;           Cin = 256; src = w_off1; dst_s = wf16 + WF_OFF1 + j; }
    else if (i < 1253376) { j = i - 1179648; Cin = 64;  src = w_off2; dst_s = wf16 + WF_OFF2 + j; }
    else if (i < 1400832) { j = i - 1253376; Cin = 256; src = w1;     dst_h = wfh + WB_C1 + j; dst_l = wfl + WB_C1 + j; }
    else                  { j = i - 1400832; Cin = 64;  src = w2;     dst_h = wfh + WB_C2 + j; dst_l = wfl + WB_C2 + j; }
    int oc  = j / (Cin * 9);
    int r   = j - oc * (Cin * 9);
    int tap = r / Cin;
    int ic  = r - tap * Cin;
    float v = src[(long long)(oc * Cin + ic) * 9 + tap];
    if (dst_s) {
        *dst_s = __float2half(v);
    } else {
        __half hi = __float2half(v);
        *dst_h = hi;
        *dst_l = __float2half(v - __half2float(hi));
    }
}

// ---------------- staging ----------------
template<int MI>
__device__ __forceinline__ void stage_A(
    uint32_t abase, int tid, int ic0, int n, int y0, int Cin,
    const __half* __restrict__ xA)
{
    constexpr int AR = (MI + 2) * 66;
    for (int i = tid; i < AR * 8; i += 256) {
        int row = i >> 3, u = i & 7;
        int rel_y = row / 66, rel_x = row - rel_y * 66;
        int ys = y0 - 1 + rel_y, xs = rel_x - 1;
        bool ok = ((unsigned)ys < 64u) && ((unsigned)xs < 64u);
        const __half* src = ok ?
            xA + (((long long)n * 4096 + ys * 64 + xs) * Cin + ic0 + (u << 3)) : xA;
        cpa16(abase + row * ROWB + (u << 4), src, ok ? 16u : 0u);
    }
}

// stage 3 taps of B: layout [pre][tap_local][oc_row]
template<int NOC, bool BSPL>
__device__ __forceinline__ void stage_B3(
    uint32_t bbase, int tid, int trio, int ic0, int oc0, int Cin,
    const __half* __restrict__ wh, const __half* __restrict__ wl)
{
    constexpr int PLANE = 3 * NOC * 8;
    const int TOT = PLANE * (BSPL ? 2 : 1);
    for (int i = tid; i < TOT; i += 256) {
        int pre = BSPL ? (i >= PLANE) : 0;
        int f   = i - pre * PLANE;
        int tl  = f / (NOC * 8);
        int g   = f - tl * (NOC * 8);
        int r = g >> 3, u = g & 7;
        int tap = trio * 3 + tl;
        const __half* src = (pre ? wl : wh) +
            ((long long)(oc0 + r) * 9 + tap) * Cin + ic0 + (u << 3);
        cpa16(bbase + (pre * 3 + tl) * (NOC * ROWB) + r * ROWB + (u << 4), src, 16u);
    }
}

// ---------------- mma implicit-GEMM conv: D[64*MI px][NOC oc] ----------------
// A halo plane double-buffered by ic64 parity; tap shift via fragment address.
// B trio double-buffered by stage parity; uniform WAIT1 pipeline (no full drain).
// BSPL: w hi/lo -> 2 passes. OFF16: NCHW output written fp16.
template<int NOC, int MI, bool BSPL, bool OFF16>
__global__ __launch_bounds__(256)
void k_conv_mma(const __half* __restrict__ xA,
                const __half* __restrict__ wh, const __half* __restrict__ wl,
                void* __restrict__ out_nchw, __half* __restrict__ out_h16,
                const float* __restrict__ bng, const float* __restrict__ bnb,
                const float* __restrict__ bnm, const float* __restrict__ bnv,
                int Cin, int Cout, int outTrans)
{
    extern __shared__ __align__(16) char smc[];
    const uint32_t uS = smem_u32(smc);

    constexpr int NT = 64 / MI;
    constexpr int AB = (MI + 2) * 66 * ROWB;            // 57024 (MI=4)
    constexpr int BB = 3 * NOC * ROWB * (BSPL ? 2 : 1); // 55296 both variants
    constexpr int J2 = NOC / 32;

    const int tid  = threadIdx.x;
    const int lane = tid & 31;
    const int wid  = tid >> 5;
    const int wm   = wid >> 1;
    const int wn   = wid & 1;

    const int n   = blockIdx.x / NT;
    const int mt  = blockIdx.x - n * NT;
    const int y0  = mt * MI;
    const int oc0 = blockIdx.y * NOC;
    const int nic = Cin >> 6;
    const int nstage = 3 * nic;

    float acc[MI][J2 * 2][4];
#pragma unroll
    for (int i = 0; i < MI; i++)
#pragma unroll
        for (int j = 0; j < J2 * 2; j++)
#pragma unroll
            for (int q = 0; q < 4; q++) acc[i][j][q] = 0.f;

    const int aOff = (lane >> 4) << 4;
    int rowoff[MI];
#pragma unroll
    for (int i = 0; i < MI; i++) {
        int m = wm * (16 * MI) + (lane & 15) + i * 16;
        rowoff[i] = (((m >> 6) + 1) * 66 + (m & 63) + 1) * ROWB;
    }
    const int bRow = wn * (NOC >> 1) + (lane & 7) + ((lane >> 4) << 3);
    const int bOff = ((lane >> 3) & 1) << 4;

    const uint32_t uA[2] = {uS, uS + AB};
    const uint32_t uB[2] = {uS + 2 * AB, uS + 2 * AB + BB};

    // prologue: A chunk 0 + B trio 0
    stage_A<MI>(uA[0], tid, 0, n, y0, Cin, xA);
    stage_B3<NOC, BSPL>(uB[0], tid, 0, 0, oc0, Cin, wh, wl);
    CPA_COMMIT();

    for (int s = 0; s < nstage; s++) {
        const int icc  = s / 3;
        const int trio = s - icc * 3;
        const int nx = s + 1;
        if (nx < nstage) {
            const int nicc = nx / 3;
            const int ntrio = nx - nicc * 3;
            if (ntrio == 0)
                stage_A<MI>(uA[nicc & 1], tid, nicc << 6, n, y0, Cin, xA);
            stage_B3<NOC, BSPL>(uB[nx & 1], tid, ntrio, nicc << 6, oc0, Cin, wh, wl);
        }
        CPA_COMMIT();
        CPA_WAIT1();
        __syncthreads();

        const uint32_t aBase = uA[icc & 1];
        const uint32_t bBase = uB[s & 1];
#pragma unroll
        for (int tl = 0; tl < 3; tl++) {
            const int tap = trio * 3 + tl;
            const int d144 = ((tap / 3) * 66 + (tap - (tap / 3) * 3) - 67) * ROWB;
            const uint32_t aH = aBase + d144;
            const uint32_t bH = bBase + tl * (NOC * ROWB);
            const uint32_t bL = bBase + (3 + tl) * (NOC * ROWB);

#pragma unroll
            for (int ks = 0; ks < 4; ks++) {
                const int kbyte = ks * 32;
                uint32_t ah[MI][4], bh[J2][4];
#pragma unroll
                for (int i = 0; i < MI; i++)
                    ldsm_x4(ah[i][0], ah[i][1], ah[i][2], ah[i][3],
                            aH + rowoff[i] + kbyte + aOff);
#pragma unroll
                for (int j2 = 0; j2 < J2; j2++)
                    ldsm_x4(bh[j2][0], bh[j2][1], bh[j2][2], bh[j2][3],
                            bH + (bRow + j2 * 16) * ROWB + kbyte + bOff);
#pragma unroll
                for (int i = 0; i < MI; i++)
#pragma unroll
                    for (int j2 = 0; j2 < J2; j2++) {
                        mma_f16(acc[i][j2 * 2 + 0], ah[i], &bh[j2][0]);
                        mma_f16(acc[i][j2 * 2 + 1], ah[i], &bh[j2][2]);
                    }
                if constexpr (BSPL) {
                    uint32_t bl[J2][4];
#pragma unroll
                    for (int j2 = 0; j2 < J2; j2++)
                        ldsm_x4(bl[j2][0], bl[j2][1], bl[j2][2], bl[j2][3],
                                bL + (bRow + j2 * 16) * ROWB + kbyte + bOff);
#pragma unroll
                    for (int i = 0; i < MI; i++)
#pragma unroll
                        for (int j2 = 0; j2 < J2; j2++) {
                            mma_f16(acc[i][j2 * 2 + 0], ah[i], &bl[j2][0]);
                            mma_f16(acc[i][j2 * 2 + 1], ah[i], &bl[j2][2]);
                        }
                }
            }
        }
        __syncthreads();
    }

    // epilogue
    const bool dobn = (bng != nullptr);
    const int qrow = lane >> 2;
    const int qcol = (lane & 3) << 1;
    const long long pixbase = (long long)mt * (64 * MI) + wm * (16 * MI);
    const int b = n >> 3, tt = n & 7;
#pragma unroll
    for (int i = 0; i < MI; i++) {
#pragma unroll
        for (int j = 0; j < J2 * 2; j++) {
            int oc = oc0 + wn * (NOC >> 1) + j * 8 + qcol;
            long long p0 = pixbase + i * 16 + qrow;
            float v0 = acc[i][j][0], v1 = acc[i][j][1];
            float v2 = acc[i][j][2], v3 = acc[i][j][3];
            if (dobn) {
                float sc0 = bng[oc] * rsqrtf(bnv[oc] + 1e-5f);
                float bi0 = bnb[oc] - bnm[oc] * sc0;
                float sc1 = bng[oc + 1] * rsqrtf(bnv[oc + 1] + 1e-5f);
                float bi1 = bnb[oc + 1] - bnm[oc + 1] * sc1;
                v0 = v0 * sc0 + bi0; v0 = (v0 > 0.f) ? v0 : 0.01f * v0;
                v1 = v1 * sc1 + bi1; v1 = (v1 > 0.f) ? v1 : 0.01f * v1;
                v2 = v2 * sc0 + bi0; v2 = (v2 > 0.f) ? v2 : 0.01f * v2;
                v3 = v3 * sc1 + bi1; v3 = (v3 > 0.f) ? v3 : 0.01f * v3;
            }
            if (out_nchw) {
                long long o0, o1;
                if (outTrans) {
                    o0 = ((((long long)b * Cout + oc) * 8 + tt) << 12) + p0;
                    o1 = ((((long long)b * Cout + oc + 1) * 8 + tt) << 12) + p0;
                } else {
                    o0 = (((long long)n * Cout + oc) << 12) + p0;
                    o1 = (((long long)n * Cout + oc + 1) << 12) + p0;
                }
                if constexpr (OFF16) {
                    __half* o = (__half*)out_nchw;
                    o[o0]     = __float2half(v0);
                    o[o1]     = __float2half(v1);
                    o[o0 + 8] = __float2half(v2);
                    o[o1 + 8] = __float2half(v3);
                } else {
                    float* o = (float*)out_nchw;
                    o[o0]     = v0;
                    o[o1]     = v1;
                    o[o0 + 8] = v2;
                    o[o1 + 8] = v3;
                }
            }
            if (out_h16) {
                long long q0 = ((long long)n * 4096 + p0) * Cout + oc;
                long long q1 = ((long long)n * 4096 + p0 + 8) * Cout + oc;
                *(__half2*)(out_h16 + q0) = __floats2half2_rn(v0, v1);
                *(__half2*)(out_h16 + q1) = __floats2half2_rn(v2, v3);
            }
        }
    }
}

// ---------------- deform -> NHWC fp16 (offsets read as __half2) ----------------
__global__ void k_deform_nhwc(const float* __restrict__ src, const __half* __restrict__ off,
                              __half* __restrict__ oh, int C, int isX)
{
    __shared__ float sv[64][33];
    const int n    = blockIdx.z;
    const int c0   = blockIdx.y << 6;
    const int pix0 = blockIdx.x << 5;
    const int tx = threadIdx.x, ty = threadIdx.y;

    const int pix = pix0 + tx;
    const int h = pix >> 6, w = pix & 63;
    const float hf = (float)h, wf = (float)w;
    const int b = n >> 3, t = n & 7;
#pragma unroll
    for (int q = 0; q < 8; q++) {
        int c = c0 + q * 8 + ty;
        // vector offset load: (oy,ox) adjacent fp16 -> one 4B coalesced load
        const __half2* offp = (const __half2*)(off + (((long long)n * C + c) << 13)) + pix;
        float2 o2 = __half22float2(*offp);
        float cy = fminf(fmaxf(hf + o2.x, 0.f), 63.f);
        float cx = fminf(fmaxf(wf + o2.y, 0.f), 63.f);
        float y0f = floorf(cy), x0f = floorf(cx);
        float tyf = cy - y0f, txf = cx - x0f;
        int y0 = (int)y0f, x0 = (int)x0f;
        int y1 = min(y0 + 1, 63), x1 = min(x0 + 1, 63);
        const float* xc = isX
            ? src + ((((long long)b * 256 + c) * 8 + t) << 12)
            : src + (((long long)n * C + c) << 12);
        float v00 = xc[(y0 << 6) + x0];
        float v01 = xc[(y0 << 6) + x1];
        float v10 = xc[(y1 << 6) + x0];
        float v11 = xc[(y1 << 6) + x1];
        sv[q * 8 + ty][tx] =
            v00 * (1.f - tyf) * (1.f - txf) + v01 * (1.f - tyf) * txf +
            v10 * tyf * (1.f - txf)         + v11 * tyf * txf;
    }
    __syncthreads();

    const int tid = ty * 32 + tx;
    const int pl  = tid >> 3;
    const int cb  = (tid & 7) << 3;
    __half hv[8];
#pragma unroll
    for (int k = 0; k < 8; k++)
        hv[k] = __float2half(sv[cb + k][pl]);
    long long o = ((long long)n * 4096 + pix0 + pl) * C + c0 + cb;
    *(uint4*)(oh + o) = *(uint4*)hv;
}

// ---------------- launch ----------------
extern "C" void kernel_launch(void* const* d_in, const int* in_sizes, int n_in,
                              void* d_out, int out_size)
{
    const float* x      = (const float*)d_in[0];
    const float* w_off1 = (const float*)d_in[3];
    const float* w1     = (const float*)d_in[4];
    const float* g1     = (const float*)d_in[5];
    const float* b1     = (const float*)d_in[6];
    const float* m1     = (const float*)d_in[7];
    const float* v1     = (const float*)d_in[8];
    const float* w_off2 = (const float*)d_in[9];
    const float* w2     = (const float*)d_in[10];
    const float* g2     = (const float*)d_in[11];
    const float* b2     = (const float*)d_in[12];
    const float* m2     = (const float*)d_in[13];
    const float* v2     = (const float*)d_in[14];
    float* out = (float*)d_out;

    float *c1;
    __half *off1h, *off2h, *xf16, *cf16, *dh1, *dh2, *wf16, *wfh, *wfl;
    cudaGetSymbolAddress((void**)&off1h, g_off1h);
    cudaGetSymbolAddress((void**)&c1,    g_c1);
    cudaGetSymbolAddress((void**)&off2h, g_off2h);
    cudaGetSymbolAddress((void**)&xf16,  g_xf16);
    cudaGetSymbolAddress((void**)&cf16,  g_cf16);
    cudaGetSymbolAddress((void**)&dh1,   g_dh1);
    cudaGetSymbolAddress((void**)&dh2,   g_dh2);
    cudaGetSymbolAddress((void**)&wf16,  g_wf16);
    cudaGetSymbolAddress((void**)&wfh,   g_wfh);
    cudaGetSymbolAddress((void**)&wfl,   g_wfl);

    // smem: A dbuf 2*57024 + B dbuf 2*55296 = 224640 (both variants)
    const int SM_ALL = 2 * 6 * 66 * ROWB + 2 * 3 * 128 * ROWB;   // 224640

    cudaFuncSetAttribute(k_conv_mma<128, 4, false, true>,
                         cudaFuncAttributeMaxDynamicSharedMemorySize, SM_ALL);
    cudaFuncSetAttribute(k_conv_mma<64, 4, true, false>,
                         cudaFuncAttributeMaxDynamicSharedMemorySize, SM_ALL);

    // preps
    k_prep_x16<<<dim3(128, 8, NIMG), dim3(32, 8)>>>(x, xf16);
    k_prep_w_all<<<(1437696 + 255) / 256, 256>>>(w_off1, w1, w_off2, w2, wf16, wfh, wfl);

    // off1: 256 -> 512 (1-pass fp16, fp16 NCHW offsets out)
    k_conv_mma<128, 4, false, true><<<dim3(NIMG * 16, 4), 256, SM_ALL>>>(
        xf16, wf16 + WF_OFF1, nullptr, off1h, nullptr,
        nullptr, nullptr, nullptr, nullptr, 256, 512, 0);

    // deform1 (reads original x) -> NHWC fp16 (C=256)
    k_deform_nhwc<<<dim3(128, 4, NIMG), dim3(32, 8)>>>(x, off1h, dh1, 256, 1);

    // conv1 + bn1 + lrelu: 256 -> 64 (2-pass w-split; f32 NCHW + fp16 NHWC out)
    k_conv_mma<64, 4, true, false><<<dim3(NIMG * 16, 1), 256, SM_ALL>>>(
        dh1, wfh + WB_C1, wfl + WB_C1, c1, cf16,
        g1, b1, m1, v1, 256, 64, 0);

    // off2: 64 -> 128 (1-pass fp16)
    k_conv_mma<128, 4, false, true><<<dim3(NIMG * 16, 1), 256, SM_ALL>>>(
        cf16, wf16 + WF_OFF2, nullptr, off2h, nullptr,
        nullptr, nullptr, nullptr, nullptr, 64, 128, 0);

    // deform2 -> NHWC fp16 (C=64)
    k_deform_nhwc<<<dim3(128, 1, NIMG), dim3(32, 8)>>>(c1, off2h, dh2, 64, 0);

    // conv2 + bn2 + lrelu + transpose: 64 -> 64 (2-pass)
    k_conv_mma<64, 4, true, false><<<dim3(NIMG * 16, 1), 256, SM_ALL>>>(
        dh2, wfh + WB_C2, wfl + WB_C2, out, nullptr,
        g2, b2, m2, v2, 64, 64, 1);
}